// round 3
// baseline (speedup 1.0000x reference)
#include <cuda_runtime.h>
#include <cuda_bf16.h>
#include <cstdint>

// ---------------- problem constants ----------------
#define BATCH 8
#define CCH   64
#define HH    64
#define WW    64
#define NPOS  4096
#define LSEQ  77
#define DTXT  512
#define NBLK  16
#define NHEAD 8
#define HDIM  8

typedef unsigned long long ull;

// packed f32x2 helpers
__device__ __forceinline__ ull pk2(float lo, float hi) {
    ull r; asm("mov.b64 %0, {%1, %2};" : "=l"(r) : "f"(lo), "f"(hi)); return r;
}
__device__ __forceinline__ void upk2(float& lo, float& hi, ull v) {
    asm("mov.b64 {%0, %1}, %2;" : "=f"(lo), "=f"(hi) : "l"(v));
}
__device__ __forceinline__ void fma2(ull& d, ull a, ull b) {
    asm("fma.rn.f32x2 %0, %1, %2, %0;" : "+l"(d) : "l"(a), "l"(b));
}
__device__ __forceinline__ ull mul2(ull a, ull b) {
    ull d; asm("mul.rn.f32x2 %0, %1, %2;" : "=l"(d) : "l"(a), "l"(b)); return d;
}
union F4 { float4 v; ull u[2]; };

// ---------------- device scratch ----------------
__device__ float g_tf  [BATCH*LSEQ*CCH];
__device__ float g_kn  [NBLK*BATCH*LSEQ*CCH];
__device__ float g_v   [NBLK*BATCH*LSEQ*CCH];
__device__ float g_feat[BATCH*CCH*HH*WW];
__device__ float g_u1  [BATCH*CCH*128*128];
__device__ float g_u2  [(size_t)BATCH*CCH*256*256];
__device__ float g_wupT[2*64*9*256];

// ---------------- text projection (+ fused up-weight transpose) ----------------
__global__ void k_textproj(const float* __restrict__ th,
                           const float* __restrict__ pw,
                           const float* __restrict__ pb,
                           const float* __restrict__ upw) {
    __shared__ float s[DTXT];
    int bl = blockIdx.x;
    const float* row = th + (size_t)bl * DTXT;
    for (int i = threadIdx.x; i < DTXT; i += 64) s[i] = row[i];
    __syncthreads();
    int c = threadIdx.x;
    const float* w = pw + (size_t)c * DTXT;
    float acc = pb[c];
#pragma unroll 8
    for (int d = 0; d < DTXT; ++d) acc += s[d] * w[d];
    g_tf[bl * CCH + c] = acc;
    // fused: transpose up weights [lvl,oc4,ic,k] -> [lvl,ic,k,oc4]
    for (int idx = blockIdx.x * 64 + threadIdx.x; idx < 2 * 256 * 64 * 9;
         idx += gridDim.x * 64) {
        int k = idx % 9;
        int t = idx / 9;
        int ic = t % 64; t /= 64;
        int oc4 = t % 256;
        int lvl = t / 256;
        g_wupT[(((lvl * 64 + ic) * 9 + k) * 256) + oc4] = upw[idx];
    }
}

// ---------------- input conv 3->64, 3x3 ----------------
__global__ void k_convin(const float* __restrict__ x,
                         const float* __restrict__ w,
                         const float* __restrict__ bias) {
    __shared__ float sw[64 * 27];
    __shared__ float sb[64];
    __shared__ float sin_[3][3][66];
    int bid = blockIdx.x; int b = bid >> 6; int y = bid & 63;
    int tid = threadIdx.x;
    for (int i = tid; i < 64 * 27; i += 64) sw[i] = w[i];
    sb[tid] = bias[tid];
    for (int ic = 0; ic < 3; ic++)
        for (int r = 0; r < 3; r++) {
            int yy = y + r - 1;
            float v = 0.f;
            if (yy >= 0 && yy < HH) v = x[(((size_t)b * 3 + ic) * HH + yy) * WW + tid];
            sin_[ic][r][tid + 1] = v;
            if (tid == 0) { sin_[ic][r][0] = 0.f; sin_[ic][r][65] = 0.f; }
        }
    __syncthreads();
    int xx = tid;
    for (int oc = 0; oc < 64; oc++) {
        float acc = sb[oc];
#pragma unroll
        for (int ic = 0; ic < 3; ic++)
#pragma unroll
            for (int r = 0; r < 3; r++)
#pragma unroll
                for (int kx = 0; kx < 3; kx++)
                    acc += sin_[ic][r][xx + kx] * sw[(oc * 3 + ic) * 9 + r * 3 + kx];
        g_feat[(((size_t)b * CCH + oc) * HH + y) * WW + xx] = acc;
    }
}

// ---------------- K/V projection + LN(K), all blocks, L-split ----------------
__global__ void __launch_bounds__(256) k_kvall(
        const float* __restrict__ kw, const float* __restrict__ kb,
        const float* __restrict__ vw, const float* __restrict__ vb,
        const float* __restrict__ l2w, const float* __restrict__ l2b) {
    __shared__ float tfs[LSEQ * 64];
    __shared__ float kws[64 * 68];
    __shared__ float vws[64 * 68];
    __shared__ float ksm[4 * 64];
    int blk = blockIdx.x, b = blockIdx.y, z = blockIdx.z;
    int tid = threadIdx.x;
    for (int i = tid; i < LSEQ * 64; i += 256) tfs[i] = g_tf[b * LSEQ * 64 + i];
    for (int idx = tid; idx < 4096; idx += 256) {
        int o = idx >> 6, c = idx & 63;
        kws[c * 68 + o] = kw[blk * 4096 + idx];
        vws[c * 68 + o] = vw[blk * 4096 + idx];
    }
    __syncthreads();
    int o = tid & 63, rr = tid >> 6;
    float kbv = kb[blk * 64 + o], vbv = vb[blk * 64 + o];
    float lwv = l2w[blk * 64 + o], lbv = l2b[blk * 64 + o];
    size_t base = ((size_t)(blk * BATCH + b)) * LSEQ * 64;
    int rbeg = z * 40, rend = rbeg + 40;
    for (int r0 = rbeg; r0 < rend; r0 += 4) {
        int r = r0 + rr;
        bool act = r < LSEQ;
        float ka = kbv, va = vbv;
        if (act) {
#pragma unroll 8
            for (int c = 0; c < 64; c++) {
                float t = tfs[r * 64 + c];
                ka += t * kws[c * 68 + o];
                va += t * vws[c * 68 + o];
            }
            ksm[rr * 64 + o] = ka;
        }
        __syncthreads();
        if (act) {
            float m = 0.f;
#pragma unroll 8
            for (int i = 0; i < 64; i++) m += ksm[rr * 64 + i];
            m *= (1.f / 64.f);
            float vv = 0.f;
#pragma unroll 8
            for (int i = 0; i < 64; i++) { float d = ksm[rr * 64 + i] - m; vv += d * d; }
            vv *= (1.f / 64.f);
            float rs = rsqrtf(vv + 1e-5f);
            g_kn[base + r * 64 + o] = (ka - m) * rs * lwv + lbv;
            g_v [base + r * 64 + o] = va;
        }
        __syncthreads();
    }
}

// ---------------- FUSED attention stack (16 blocks, one launch) ----------------
// smem aliasing: rA = {Wq | K}, rB = {V | Wo}. 73.2KB -> 3 CTAs/SM.
__global__ void __launch_bounds__(256, 3) k_attn_stack(
        const float* __restrict__ qw, const float* __restrict__ qb,
        const float* __restrict__ ow, const float* __restrict__ ob,
        const float* __restrict__ l1w, const float* __restrict__ l1b) {
    __shared__ __align__(16) float rA[LSEQ * 64];   // Wq[i*68+o] | K[l*64+c]
    __shared__ __align__(16) float rB[LSEQ * 64];   // V[l*64+c] | Wo[i*68+o]
    __shared__ __align__(16) float sF[64 * 64];     // feat [i][x]
    __shared__ __align__(16) float sQ[64 * 68];     // qn[x][c] then aoT[c][x]

    int b = blockIdx.x >> 6, y = blockIdx.x & 63;
    int tid = threadIdx.x;

    for (int idx = tid; idx < 4096; idx += 256)
        sF[idx] = g_feat[(((size_t)b * 64 + (idx >> 6)) * 64 + y) * 64 + (idx & 63)];

    float pey = (float)y * (0.05f / 63.f);
    const float scale = 0.35355339059327373f;

#pragma unroll 1
    for (int blk = 0; blk < NBLK; blk++) {
        size_t kvbase = ((size_t)(blk * BATCH + b)) * LSEQ * 64;
        __syncthreads();
        // load Wq -> rA, V -> rB
        for (int idx = tid; idx < 4096; idx += 256) {
            int o = idx >> 6, i = idx & 63;
            rA[i * 68 + o] = qw[blk * 4096 + idx];
        }
        for (int i = tid; i < LSEQ * 64; i += 256) rB[i] = g_v[kvbase + i];
        __syncthreads();

        // ---- phase B: q-proj + pe + LN -> sQ[x][c] ----
        {
            int og = tid & 15, xg = tid >> 4;
            int o0 = og * 4, x0 = xg * 4;
            float4 bq = *(const float4*)&qb[blk * 64 + o0];
            ull acc2[4][2];   // [xi][oj-pair]
#pragma unroll
            for (int xi = 0; xi < 4; xi++) {
                acc2[xi][0] = pk2(bq.x, bq.y);
                acc2[xi][1] = pk2(bq.z, bq.w);
            }
#pragma unroll 8
            for (int i = 0; i < 64; i++) {
                float4 fx = *(const float4*)&sF[i * 64 + x0];
                F4 wv; wv.v = *(const float4*)&rA[i * 68 + o0];
                ull f0 = pk2(fx.x, fx.x), f1 = pk2(fx.y, fx.y);
                ull f2 = pk2(fx.z, fx.z), f3 = pk2(fx.w, fx.w);
                fma2(acc2[0][0], wv.u[0], f0); fma2(acc2[0][1], wv.u[1], f0);
                fma2(acc2[1][0], wv.u[0], f1); fma2(acc2[1][1], wv.u[1], f1);
                fma2(acc2[2][0], wv.u[0], f2); fma2(acc2[2][1], wv.u[1], f2);
                fma2(acc2[3][0], wv.u[0], f3); fma2(acc2[3][1], wv.u[1], f3);
            }
            float4 lw = *(const float4*)&l1w[blk * 64 + o0];
            float4 lb = *(const float4*)&l1b[blk * 64 + o0];
#pragma unroll
            for (int xi = 0; xi < 4; xi++) {
                float a0, a1, a2, a3;
                upk2(a0, a1, acc2[xi][0]);
                upk2(a2, a3, acc2[xi][1]);
                float pex = (float)(x0 + xi) * (0.05f / 63.f);
                a0 += ((o0 + 0) < 32) ? pex : pey;
                a1 += ((o0 + 1) < 32) ? pex : pey;
                a2 += ((o0 + 2) < 32) ? pex : pey;
                a3 += ((o0 + 3) < 32) ? pex : pey;
                float s = a0 + a1 + a2 + a3;
#pragma unroll
                for (int off = 1; off < 16; off <<= 1) s += __shfl_xor_sync(0xffffffffu, s, off);
                float mean = s * (1.f / 64.f);
                float d0 = a0 - mean, d1 = a1 - mean, d2 = a2 - mean, d3 = a3 - mean;
                float sq = d0 * d0 + d1 * d1 + d2 * d2 + d3 * d3;
#pragma unroll
                for (int off = 1; off < 16; off <<= 1) sq += __shfl_xor_sync(0xffffffffu, sq, off);
                float rs = rsqrtf(sq * (1.f / 64.f) + 1e-5f);
                float4 outv;
                outv.x = d0 * rs * lw.x + lb.x;
                outv.y = d1 * rs * lw.y + lb.y;
                outv.z = d2 * rs * lw.z + lb.z;
                outv.w = d3 * rs * lw.w + lb.w;
                *(float4*)&sQ[(x0 + xi) * 68 + o0] = outv;
            }
        }
        __syncthreads();
        // load K -> rA (Wq dead)
        for (int i = tid; i < LSEQ * 64; i += 256) rA[i] = g_kn[kvbase + i];
        __syncthreads();

        // ---- phase C: attention ----
        {
            int hp = tid & 3, pl = tid >> 2;
            int co = hp * 16;
            F4 qa0, qa1, qb0, qb1;
            const float4* qp = (const float4*)&sQ[pl * 68 + co];
            qa0.v = qp[0]; qa1.v = qp[1]; qb0.v = qp[2]; qb1.v = qp[3];
            __syncthreads();   // all q reads done before aoT overwrites sQ
            float denA = 0.f, denB = 0.f;
            ull oA[4], oB[4];
            ull z0 = pk2(0.f, 0.f);
#pragma unroll
            for (int c = 0; c < 4; c++) { oA[c] = z0; oB[c] = z0; }
            for (int l = 0; l < LSEQ; l++) {
                F4 k0, k1, k2, k3;
                const float4* kp = (const float4*)&rA[l * 64 + co];
                k0.v = kp[0]; k1.v = kp[1]; k2.v = kp[2]; k3.v = kp[3];
                ull lgA2 = mul2(qa0.u[0], k0.u[0]);
                fma2(lgA2, qa0.u[1], k0.u[1]);
                fma2(lgA2, qa1.u[0], k1.u[0]);
                fma2(lgA2, qa1.u[1], k1.u[1]);
                ull lgB2 = mul2(qb0.u[0], k2.u[0]);
                fma2(lgB2, qb0.u[1], k2.u[1]);
                fma2(lgB2, qb1.u[0], k3.u[0]);
                fma2(lgB2, qb1.u[1], k3.u[1]);
                float la, lb_, lc, ld;
                upk2(la, lb_, lgA2); upk2(lc, ld, lgB2);
                float eA = __expf((la + lb_) * scale);
                float eB = __expf((lc + ld) * scale);
                denA += eA; denB += eB;
                ull eA2 = pk2(eA, eA), eB2 = pk2(eB, eB);
                F4 v0, v1, v2, v3;
                const float4* vp = (const float4*)&rB[l * 64 + co];
                v0.v = vp[0]; v1.v = vp[1]; v2.v = vp[2]; v3.v = vp[3];
                fma2(oA[0], eA2, v0.u[0]); fma2(oA[1], eA2, v0.u[1]);
                fma2(oA[2], eA2, v1.u[0]); fma2(oA[3], eA2, v1.u[1]);
                fma2(oB[0], eB2, v2.u[0]); fma2(oB[1], eB2, v2.u[1]);
                fma2(oB[2], eB2, v3.u[0]); fma2(oB[3], eB2, v3.u[1]);
            }
            float iA = 1.f / denA, iB = 1.f / denB;
#pragma unroll
            for (int c = 0; c < 4; c++) {
                float lo, hi;
                upk2(lo, hi, oA[c]);
                sQ[(co + 2 * c + 0) * 68 + pl] = lo * iA;
                sQ[(co + 2 * c + 1) * 68 + pl] = hi * iA;
            }
#pragma unroll
            for (int c = 0; c < 4; c++) {
                float lo, hi;
                upk2(lo, hi, oB[c]);
                sQ[(co + 8 + 2 * c + 0) * 68 + pl] = lo * iB;
                sQ[(co + 8 + 2 * c + 1) * 68 + pl] = hi * iB;
            }
        }
        __syncthreads();
        // load Wo -> rB (V dead)
        for (int idx = tid; idx < 4096; idx += 256) {
            int o = idx >> 6, i = idx & 63;
            rB[i * 68 + o] = ow[blk * 4096 + idx];
        }
        __syncthreads();

        // ---- phase E: out-proj + residual -> sF ----
        {
            int xg = tid & 15, og = tid >> 4;
            int x0 = xg * 4, o0 = og * 4;
            ull acc2[4][2];   // [xi][oj-pair]
            ull z0 = pk2(0.f, 0.f);
#pragma unroll
            for (int xi = 0; xi < 4; xi++) { acc2[xi][0] = z0; acc2[xi][1] = z0; }
#pragma unroll 8
            for (int i = 0; i < 64; i++) {
                float4 fx = *(const float4*)&sQ[i * 68 + x0];
                F4 wv; wv.v = *(const float4*)&rB[i * 68 + o0];
                ull f0 = pk2(fx.x, fx.x), f1 = pk2(fx.y, fx.y);
                ull f2 = pk2(fx.z, fx.z), f3 = pk2(fx.w, fx.w);
                fma2(acc2[0][0], wv.u[0], f0); fma2(acc2[0][1], wv.u[1], f0);
                fma2(acc2[1][0], wv.u[0], f1); fma2(acc2[1][1], wv.u[1], f1);
                fma2(acc2[2][0], wv.u[0], f2); fma2(acc2[2][1], wv.u[1], f2);
                fma2(acc2[3][0], wv.u[0], f3); fma2(acc2[3][1], wv.u[1], f3);
            }
            float4 bo = *(const float4*)&ob[blk * 64 + o0];
            float acc[4][4];  // [oj][xi]
#pragma unroll
            for (int xi = 0; xi < 4; xi++) {
                upk2(acc[0][xi], acc[1][xi], acc2[xi][0]);
                upk2(acc[2][xi], acc[3][xi], acc2[xi][1]);
            }
            float bov[4] = { bo.x, bo.y, bo.z, bo.w };
            __syncthreads();
#pragma unroll
            for (int oj = 0; oj < 4; oj++) {
                float* fp = &sF[(o0 + oj) * 64 + x0];
                float4 f = *(float4*)fp;
                f.x += acc[oj][0] + bov[oj];
                f.y += acc[oj][1] + bov[oj];
                f.z += acc[oj][2] + bov[oj];
                f.w += acc[oj][3] + bov[oj];
                *(float4*)fp = f;
            }
        }
    }
    __syncthreads();
    for (int idx = tid; idx < 4096; idx += 256)
        g_feat[(((size_t)b * 64 + (idx >> 6)) * 64 + y) * 64 + (idx & 63)] = sF[idx];
}

// ---------------- up-sample conv + pixel-shuffle + relu (FFMA2) ----------------
__global__ void __launch_bounds__(256, 3) k_upconv(int lvl, int IH, int IW,
                                                   const float* __restrict__ up_b) {
    const float* in  = lvl ? g_u1 : g_feat;
    float*       outp = lvl ? g_u2 : g_u1;
    __shared__ __align__(16) float sin_[16][10][20];   // padded rows (16B-aligned)
    __shared__ __align__(16) float ws [16][9][64];
    int x0 = blockIdx.x * 16, y0 = blockIdx.y * 8;
    int bz = blockIdx.z; int b = bz >> 2; int ocg = bz & 3;
    int tid = threadIdx.x;
    int ocq = tid & 7; int pg = tid >> 3;
    int tx = (pg & 3) * 4; int ty = pg >> 2;
    int ocb = ocg * 64 + ocq * 8;
    ull acc2[4][4];   // [oc-pair p][xi]; pair p -> oc (ocb+2p, ocb+2p+1)
#pragma unroll
    for (int p = 0; p < 4; p++) {
        ull bb = pk2(up_b[lvl * 256 + ocb + 2 * p], up_b[lvl * 256 + ocb + 2 * p + 1]);
#pragma unroll
        for (int xi = 0; xi < 4; xi++) acc2[p][xi] = bb;
    }
    for (int ic0 = 0; ic0 < 64; ic0 += 16) {
        __syncthreads();
        for (int idx = tid; idx < 16 * 10 * 18; idx += 256) {
            int c = idx % 18; int r = (idx / 18) % 10; int icc = idx / 180;
            int gy = y0 - 1 + r, gx = x0 - 1 + c;
            float v = 0.f;
            if (gy >= 0 && gy < IH && gx >= 0 && gx < IW)
                v = in[(((size_t)b * 64 + ic0 + icc) * IH + gy) * IW + gx];
            sin_[icc][r][c] = v;
        }
        for (int idx = tid; idx < 16 * 9 * 64; idx += 256) {
            int oc = idx & 63; int kk = (idx >> 6) % 9; int icc = idx / 576;
            ws[icc][kk][oc] =
                g_wupT[(((lvl * 64 + icc + ic0) * 9 + kk) * 256) + ocg * 64 + oc];
        }
        __syncthreads();
        for (int icc = 0; icc < 16; icc++) {
#pragma unroll
            for (int ky = 0; ky < 3; ky++) {
                F4 ia; ia.v = *(const float4*)&sin_[icc][ty + ky][tx];
                float2 ib = *(const float2*)&sin_[icc][ty + ky][tx + 4];
                ull in2[6];
                in2[0] = pk2(ia.v.x, ia.v.x); in2[1] = pk2(ia.v.y, ia.v.y);
                in2[2] = pk2(ia.v.z, ia.v.z); in2[3] = pk2(ia.v.w, ia.v.w);
                in2[4] = pk2(ib.x, ib.x);     in2[5] = pk2(ib.y, ib.y);
#pragma unroll
                for (int kx = 0; kx < 3; kx++) {
                    F4 wA; wA.v = *(const float4*)&ws[icc][ky * 3 + kx][ocq * 8];
                    F4 wB; wB.v = *(const float4*)&ws[icc][ky * 3 + kx][ocq * 8 + 4];
#pragma unroll
                    for (int xi = 0; xi < 4; xi++) {
                        ull f = in2[kx + xi];
                        fma2(acc2[0][xi], wA.u[0], f);
                        fma2(acc2[1][xi], wA.u[1], f);
                        fma2(acc2[2][xi], wB.u[0], f);
                        fma2(acc2[3][xi], wB.u[1], f);
                    }
                }
            }
        }
    }
    int OW = IW * 2;
    int gy = y0 + ty, gxb = x0 + tx;
#pragma unroll
    for (int p = 0; p < 4; p++) {
#pragma unroll
        for (int xi = 0; xi < 4; xi++) {
            float lo, hi;
            upk2(lo, hi, acc2[p][xi]);
            int j0 = 2 * p, j1 = 2 * p + 1;
            int oc4a = ocb + j0, oc4b = ocb + j1;
            int ca = oc4a >> 2, r1a = (oc4a >> 1) & 1, r2a = oc4a & 1;
            int cb = oc4b >> 2, r1b = (oc4b >> 1) & 1, r2b = oc4b & 1;
            size_t ra = (((size_t)b * 64 + ca) * (size_t)(IH * 2) + (size_t)(2 * gy + r1a)) * (size_t)OW;
            size_t rb = (((size_t)b * 64 + cb) * (size_t)(IH * 2) + (size_t)(2 * gy + r1b)) * (size_t)OW;
            outp[ra + 2 * (gxb + xi) + r2a] = fmaxf(lo, 0.f);
            outp[rb + 2 * (gxb + xi) + r2b] = fmaxf(hi, 0.f);
        }
    }
}

// ---------------- final conv 64->3 at 256x256 ----------------
__global__ void __launch_bounds__(256) k_cl(const float* __restrict__ w,
                                            const float* __restrict__ bias,
                                            float* __restrict__ out) {
    __shared__ float sw[3 * 64 * 9];
    __shared__ float sin_[4][10][132];
    int xbase = blockIdx.x * 128;
    int y0 = blockIdx.y * 8;
    int b = blockIdx.z;
    int tid = threadIdx.x;
    int xg = tid & 31; int yr = tid >> 5;
    int x0 = xg * 4;
    for (int i = tid; i < 1728; i += 256) sw[i] = w[i];
    float acc[3][4];
#pragma unroll
    for (int oc = 0; oc < 3; oc++) {
        float bb = bias[oc];
#pragma unroll
        for (int xi = 0; xi < 4; xi++) acc[oc][xi] = bb;
    }
    for (int ic0 = 0; ic0 < 64; ic0 += 4) {
        __syncthreads();
        for (int idx = tid; idx < 4 * 10 * 130; idx += 256) {
            int c = idx % 130; int r = (idx / 130) % 10; int icc = idx / 1300;
            int gy = y0 - 1 + r, gx = xbase - 1 + c;
            float v = 0.f;
            if (gy >= 0 && gy < 256 && gx >= 0 && gx < 256)
                v = g_u2[(((size_t)b * 64 + ic0 + icc) * 256 + gy) * 256 + gx];
            sin_[icc][r][c] = v;
        }
        __syncthreads();
        for (int icc = 0; icc < 4; icc++) {
#pragma unroll
            for (int ky = 0; ky < 3; ky++) {
                float in6[6];
#pragma unroll
                for (int t = 0; t < 6; t++) in6[t] = sin_[icc][yr + ky][x0 + t];
#pragma unroll
                for (int kx = 0; kx < 3; kx++) {
#pragma unroll
                    for (int oc = 0; oc < 3; oc++) {
                        float wv = sw[(oc * 64 + ic0 + icc) * 9 + ky * 3 + kx];
#pragma unroll
                        for (int xi = 0; xi < 4; xi++)
                            acc[oc][xi] += wv * in6[kx + xi];
                    }
                }
            }
        }
    }
    int gy = y0 + yr, gx0 = xbase + x0;
#pragma unroll
    for (int oc = 0; oc < 3; oc++) {
        float4 v = make_float4(acc[oc][0], acc[oc][1], acc[oc][2], acc[oc][3]);
        *(float4*)&out[(((size_t)b * 3 + oc) * 256 + gy) * 256 + gx0] = v;
    }
}

// ---------------- launcher ----------------
extern "C" void kernel_launch(void* const* d_in, const int* in_sizes, int n_in,
                              void* d_out, int out_size) {
    const float* x      = (const float*)d_in[0];
    const float* th     = (const float*)d_in[1];
    const float* proj_w = (const float*)d_in[2];
    const float* proj_b = (const float*)d_in[3];
    const float* cf_w   = (const float*)d_in[4];
    const float* cf_b   = (const float*)d_in[5];
    const float* qw     = (const float*)d_in[6];
    const float* qb     = (const float*)d_in[7];
    const float* kw     = (const float*)d_in[8];
    const float* kb     = (const float*)d_in[9];
    const float* vw     = (const float*)d_in[10];
    const float* vb     = (const float*)d_in[11];
    const float* ow     = (const float*)d_in[12];
    const float* ob     = (const float*)d_in[13];
    const float* l1w    = (const float*)d_in[14];
    const float* l1b    = (const float*)d_in[15];
    const float* l2w    = (const float*)d_in[16];
    const float* l2b    = (const float*)d_in[17];
    const float* up_w   = (const float*)d_in[18];
    const float* up_b   = (const float*)d_in[19];
    const float* cl_w   = (const float*)d_in[20];
    const float* cl_b   = (const float*)d_in[21];
    float* out = (float*)d_out;

    k_textproj<<<BATCH * LSEQ, 64>>>(th, proj_w, proj_b, up_w);
    k_convin<<<BATCH * HH, 64>>>(x, cf_w, cf_b);
    k_kvall<<<dim3(NBLK, BATCH, 2), 256>>>(kw, kb, vw, vb, l2w, l2b);
    k_attn_stack<<<BATCH * HH, 256>>>(qw, qb, ow, ob, l1w, l1b);
    k_upconv<<<dim3(4, 8, BATCH * 4), 256>>>(0, 64, 64, up_b);
    k_upconv<<<dim3(8, 16, BATCH * 4), 256>>>(1, 128, 128, up_b);
    k_cl<<<dim3(2, 32, BATCH), 256>>>(cl_w, cl_b, out);

    (void)in_sizes; (void)n_in; (void)out_size;
}

// round 4
// speedup vs baseline: 1.1571x; 1.1571x over previous
#include <cuda_runtime.h>
#include <cuda_bf16.h>
#include <cstdint>

// ---------------- problem constants ----------------
#define BATCH 8
#define CCH   64
#define HH    64
#define WW    64
#define NPOS  4096
#define LSEQ  77
#define DTXT  512
#define NBLK  16
#define NHEAD 8
#define HDIM  8

// ---------------- device scratch ----------------
__device__ float g_tf  [BATCH*LSEQ*CCH];
__device__ float g_kn  [NBLK*BATCH*LSEQ*CCH];
__device__ float g_v   [NBLK*BATCH*LSEQ*CCH];
__device__ float g_feat[BATCH*CCH*HH*WW];
__device__ float g_u1  [BATCH*CCH*128*128];
__device__ float g_u2  [(size_t)BATCH*CCH*256*256];
__device__ float g_wupT[2*64*9*256];

// ---------------- text projection (+ fused up-weight transpose) ----------------
__global__ void k_textproj(const float* __restrict__ th,
                           const float* __restrict__ pw,
                           const float* __restrict__ pb,
                           const float* __restrict__ upw) {
    __shared__ float s[DTXT];
    int bl = blockIdx.x;
    const float* row = th + (size_t)bl * DTXT;
    for (int i = threadIdx.x; i < DTXT; i += 64) s[i] = row[i];
    __syncthreads();
    int c = threadIdx.x;
    const float* w = pw + (size_t)c * DTXT;
    float acc = pb[c];
#pragma unroll 8
    for (int d = 0; d < DTXT; ++d) acc += s[d] * w[d];
    g_tf[bl * CCH + c] = acc;
    // fused: transpose up weights [lvl,oc4,ic,k] -> [lvl,ic,k,oc4]
    for (int idx = blockIdx.x * 64 + threadIdx.x; idx < 2 * 256 * 64 * 9;
         idx += gridDim.x * 64) {
        int k = idx % 9;
        int t = idx / 9;
        int ic = t % 64; t /= 64;
        int oc4 = t % 256;
        int lvl = t / 256;
        g_wupT[(((lvl * 64 + ic) * 9 + k) * 256) + oc4] = upw[idx];
    }
}

// ---------------- input conv 3->64, 3x3 ----------------
__global__ void k_convin(const float* __restrict__ x,
                         const float* __restrict__ w,
                         const float* __restrict__ bias) {
    __shared__ float sw[64 * 27];
    __shared__ float sb[64];
    __shared__ float sin_[3][3][66];
    int bid = blockIdx.x; int b = bid >> 6; int y = bid & 63;
    int tid = threadIdx.x;
    for (int i = tid; i < 64 * 27; i += 64) sw[i] = w[i];
    sb[tid] = bias[tid];
    for (int ic = 0; ic < 3; ic++)
        for (int r = 0; r < 3; r++) {
            int yy = y + r - 1;
            float v = 0.f;
            if (yy >= 0 && yy < HH) v = x[(((size_t)b * 3 + ic) * HH + yy) * WW + tid];
            sin_[ic][r][tid + 1] = v;
            if (tid == 0) { sin_[ic][r][0] = 0.f; sin_[ic][r][65] = 0.f; }
        }
    __syncthreads();
    int xx = tid;
    for (int oc = 0; oc < 64; oc++) {
        float acc = sb[oc];
#pragma unroll
        for (int ic = 0; ic < 3; ic++)
#pragma unroll
            for (int r = 0; r < 3; r++)
#pragma unroll
                for (int kx = 0; kx < 3; kx++)
                    acc += sin_[ic][r][xx + kx] * sw[(oc * 3 + ic) * 9 + r * 3 + kx];
        g_feat[(((size_t)b * CCH + oc) * HH + y) * WW + xx] = acc;
    }
}

// ---------------- K/V projection + LN(K), all blocks, L-split ----------------
__global__ void __launch_bounds__(256) k_kvall(
        const float* __restrict__ kw, const float* __restrict__ kb,
        const float* __restrict__ vw, const float* __restrict__ vb,
        const float* __restrict__ l2w, const float* __restrict__ l2b) {
    __shared__ float tfs[LSEQ * 64];
    __shared__ float kws[64 * 68];
    __shared__ float vws[64 * 68];
    __shared__ float ksm[4 * 64];
    int blk = blockIdx.x, b = blockIdx.y, z = blockIdx.z;
    int tid = threadIdx.x;
    for (int i = tid; i < LSEQ * 64; i += 256) tfs[i] = g_tf[b * LSEQ * 64 + i];
    for (int idx = tid; idx < 4096; idx += 256) {
        int o = idx >> 6, c = idx & 63;
        kws[c * 68 + o] = kw[blk * 4096 + idx];
        vws[c * 68 + o] = vw[blk * 4096 + idx];
    }
    __syncthreads();
    int o = tid & 63, rr = tid >> 6;
    float kbv = kb[blk * 64 + o], vbv = vb[blk * 64 + o];
    float lwv = l2w[blk * 64 + o], lbv = l2b[blk * 64 + o];
    size_t base = ((size_t)(blk * BATCH + b)) * LSEQ * 64;
    int rbeg = z * 40, rend = rbeg + 40;
    for (int r0 = rbeg; r0 < rend; r0 += 4) {
        int r = r0 + rr;
        bool act = r < LSEQ;
        float ka = kbv, va = vbv;
        if (act) {
#pragma unroll 8
            for (int c = 0; c < 64; c++) {
                float t = tfs[r * 64 + c];
                ka += t * kws[c * 68 + o];
                va += t * vws[c * 68 + o];
            }
            ksm[rr * 64 + o] = ka;
        }
        __syncthreads();
        if (act) {
            float m = 0.f;
#pragma unroll 8
            for (int i = 0; i < 64; i++) m += ksm[rr * 64 + i];
            m *= (1.f / 64.f);
            float vv = 0.f;
#pragma unroll 8
            for (int i = 0; i < 64; i++) { float d = ksm[rr * 64 + i] - m; vv += d * d; }
            vv *= (1.f / 64.f);
            float rs = rsqrtf(vv + 1e-5f);
            g_kn[base + r * 64 + o] = (ka - m) * rs * lwv + lbv;
            g_v [base + r * 64 + o] = va;
        }
        __syncthreads();
    }
}

// ---------------- FUSED attention stack (16 blocks, one launch) ----------------
// smem aliasing: rA = {Wq | K}, rB = {V | Wo}. 73.2KB -> 3 CTAs/SM.
__global__ void __launch_bounds__(256, 3) k_attn_stack(
        const float* __restrict__ qw, const float* __restrict__ qb,
        const float* __restrict__ ow, const float* __restrict__ ob,
        const float* __restrict__ l1w, const float* __restrict__ l1b) {
    __shared__ __align__(16) float rA[LSEQ * 64];   // Wq[i*68+o] | K[l*64+c]
    __shared__ __align__(16) float rB[LSEQ * 64];   // V[l*64+c] | Wo[i*68+o]
    __shared__ __align__(16) float sF[64 * 64];     // feat [i][x]
    __shared__ __align__(16) float sQ[64 * 68];     // qn[x][c] then aoT[c][x]

    int b = blockIdx.x >> 6, y = blockIdx.x & 63;
    int tid = threadIdx.x;

    for (int idx = tid; idx < 4096; idx += 256)
        sF[idx] = g_feat[(((size_t)b * 64 + (idx >> 6)) * 64 + y) * 64 + (idx & 63)];

    float pey = (float)y * (0.05f / 63.f);
    const float scale = 0.35355339059327373f;

#pragma unroll 1
    for (int blk = 0; blk < NBLK; blk++) {
        size_t kvbase = ((size_t)(blk * BATCH + b)) * LSEQ * 64;
        __syncthreads();
        // load Wq -> rA, V -> rB
        for (int idx = tid; idx < 4096; idx += 256) {
            int o = idx >> 6, i = idx & 63;
            rA[i * 68 + o] = qw[blk * 4096 + idx];
        }
        for (int i = tid; i < LSEQ * 64; i += 256) rB[i] = g_v[kvbase + i];
        __syncthreads();

        // ---- phase B: q-proj + pe + LN -> sQ[x][c] ----
        {
            int og = tid & 15, xg = tid >> 4;
            int o0 = og * 4, x0 = xg * 4;
            float4 bq = *(const float4*)&qb[blk * 64 + o0];
            float acc[4][4];   // [xi][oj]
#pragma unroll
            for (int xi = 0; xi < 4; xi++) {
                acc[xi][0] = bq.x; acc[xi][1] = bq.y; acc[xi][2] = bq.z; acc[xi][3] = bq.w;
            }
#pragma unroll 8
            for (int i = 0; i < 64; i++) {
                float4 fx = *(const float4*)&sF[i * 64 + x0];
                float4 wv = *(const float4*)&rA[i * 68 + o0];
                acc[0][0] += fx.x * wv.x; acc[0][1] += fx.x * wv.y; acc[0][2] += fx.x * wv.z; acc[0][3] += fx.x * wv.w;
                acc[1][0] += fx.y * wv.x; acc[1][1] += fx.y * wv.y; acc[1][2] += fx.y * wv.z; acc[1][3] += fx.y * wv.w;
                acc[2][0] += fx.z * wv.x; acc[2][1] += fx.z * wv.y; acc[2][2] += fx.z * wv.z; acc[2][3] += fx.z * wv.w;
                acc[3][0] += fx.w * wv.x; acc[3][1] += fx.w * wv.y; acc[3][2] += fx.w * wv.z; acc[3][3] += fx.w * wv.w;
            }
            float4 lw = *(const float4*)&l1w[blk * 64 + o0];
            float4 lb = *(const float4*)&l1b[blk * 64 + o0];
#pragma unroll
            for (int xi = 0; xi < 4; xi++) {
                float pex = (float)(x0 + xi) * (0.05f / 63.f);
#pragma unroll
                for (int oj = 0; oj < 4; oj++)
                    acc[xi][oj] += ((o0 + oj) < 32) ? pex : pey;
                float s = acc[xi][0] + acc[xi][1] + acc[xi][2] + acc[xi][3];
#pragma unroll
                for (int off = 1; off < 16; off <<= 1) s += __shfl_xor_sync(0xffffffffu, s, off);
                float mean = s * (1.f / 64.f);
                float d0 = acc[xi][0] - mean, d1 = acc[xi][1] - mean,
                      d2 = acc[xi][2] - mean, d3 = acc[xi][3] - mean;
                float sq = d0 * d0 + d1 * d1 + d2 * d2 + d3 * d3;
#pragma unroll
                for (int off = 1; off < 16; off <<= 1) sq += __shfl_xor_sync(0xffffffffu, sq, off);
                float rs = rsqrtf(sq * (1.f / 64.f) + 1e-5f);
                float4 outv;
                outv.x = d0 * rs * lw.x + lb.x;
                outv.y = d1 * rs * lw.y + lb.y;
                outv.z = d2 * rs * lw.z + lb.z;
                outv.w = d3 * rs * lw.w + lb.w;
                *(float4*)&sQ[(x0 + xi) * 68 + o0] = outv;
            }
        }
        __syncthreads();
        // load K -> rA (Wq dead)
        for (int i = tid; i < LSEQ * 64; i += 256) rA[i] = g_kn[kvbase + i];
        __syncthreads();

        // ---- phase C: attention. thread = (pos, head-pair) ----
        {
            int hp = tid & 3, pl = tid >> 2;
            int co = hp * 16;
            const float4* qp = (const float4*)&sQ[pl * 68 + co];
            float4 qa0 = qp[0], qa1 = qp[1], qb0 = qp[2], qb1 = qp[3];
            __syncthreads();   // all q reads done before aoT overwrites sQ
            float denA = 0.f, denB = 0.f;
            float4 a0 = make_float4(0, 0, 0, 0), a1 = a0, b0 = a0, b1 = a0;
            for (int l = 0; l < LSEQ; l++) {
                const float4* kp = (const float4*)&rA[l * 64 + co];
                float4 k0 = kp[0], k1 = kp[1], k2 = kp[2], k3 = kp[3];
                float lgA = qa0.x * k0.x + qa0.y * k0.y + qa0.z * k0.z + qa0.w * k0.w
                          + qa1.x * k1.x + qa1.y * k1.y + qa1.z * k1.z + qa1.w * k1.w;
                float lgB = qb0.x * k2.x + qb0.y * k2.y + qb0.z * k2.z + qb0.w * k2.w
                          + qb1.x * k3.x + qb1.y * k3.y + qb1.z * k3.z + qb1.w * k3.w;
                float eA = __expf(lgA * scale);
                float eB = __expf(lgB * scale);
                denA += eA; denB += eB;
                const float4* vp = (const float4*)&rB[l * 64 + co];
                float4 v0 = vp[0], v1 = vp[1], v2 = vp[2], v3 = vp[3];
                a0.x += eA * v0.x; a0.y += eA * v0.y; a0.z += eA * v0.z; a0.w += eA * v0.w;
                a1.x += eA * v1.x; a1.y += eA * v1.y; a1.z += eA * v1.z; a1.w += eA * v1.w;
                b0.x += eB * v2.x; b0.y += eB * v2.y; b0.z += eB * v2.z; b0.w += eB * v2.w;
                b1.x += eB * v3.x; b1.y += eB * v3.y; b1.z += eB * v3.z; b1.w += eB * v3.w;
            }
            float iA = 1.f / denA, iB = 1.f / denB;
            sQ[(co + 0) * 68 + pl] = a0.x * iA;  sQ[(co + 1) * 68 + pl] = a0.y * iA;
            sQ[(co + 2) * 68 + pl] = a0.z * iA;  sQ[(co + 3) * 68 + pl] = a0.w * iA;
            sQ[(co + 4) * 68 + pl] = a1.x * iA;  sQ[(co + 5) * 68 + pl] = a1.y * iA;
            sQ[(co + 6) * 68 + pl] = a1.z * iA;  sQ[(co + 7) * 68 + pl] = a1.w * iA;
            sQ[(co + 8) * 68 + pl] = b0.x * iB;  sQ[(co + 9) * 68 + pl] = b0.y * iB;
            sQ[(co + 10) * 68 + pl] = b0.z * iB; sQ[(co + 11) * 68 + pl] = b0.w * iB;
            sQ[(co + 12) * 68 + pl] = b1.x * iB; sQ[(co + 13) * 68 + pl] = b1.y * iB;
            sQ[(co + 14) * 68 + pl] = b1.z * iB; sQ[(co + 15) * 68 + pl] = b1.w * iB;
        }
        __syncthreads();
        // load Wo -> rB (V dead)
        for (int idx = tid; idx < 4096; idx += 256) {
            int o = idx >> 6, i = idx & 63;
            rB[i * 68 + o] = ow[blk * 4096 + idx];
        }
        __syncthreads();

        // ---- phase E: out-proj + residual -> sF ----
        {
            int xg = tid & 15, og = tid >> 4;
            int x0 = xg * 4, o0 = og * 4;
            float acc[4][4];   // [oj][xi]
#pragma unroll
            for (int oj = 0; oj < 4; oj++)
#pragma unroll
                for (int xi = 0; xi < 4; xi++) acc[oj][xi] = 0.f;
#pragma unroll 8
            for (int i = 0; i < 64; i++) {
                float4 fx = *(const float4*)&sQ[i * 68 + x0];
                float4 wv = *(const float4*)&rB[i * 68 + o0];
                acc[0][0] += wv.x * fx.x; acc[0][1] += wv.x * fx.y; acc[0][2] += wv.x * fx.z; acc[0][3] += wv.x * fx.w;
                acc[1][0] += wv.y * fx.x; acc[1][1] += wv.y * fx.y; acc[1][2] += wv.y * fx.z; acc[1][3] += wv.y * fx.w;
                acc[2][0] += wv.z * fx.x; acc[2][1] += wv.z * fx.y; acc[2][2] += wv.z * fx.z; acc[2][3] += wv.z * fx.w;
                acc[3][0] += wv.w * fx.x; acc[3][1] += wv.w * fx.y; acc[3][2] += wv.w * fx.z; acc[3][3] += wv.w * fx.w;
            }
            float4 bo = *(const float4*)&ob[blk * 64 + o0];
            float bov[4] = { bo.x, bo.y, bo.z, bo.w };
            __syncthreads();
#pragma unroll
            for (int oj = 0; oj < 4; oj++) {
                float* fp = &sF[(o0 + oj) * 64 + x0];
                float4 f = *(float4*)fp;
                f.x += acc[oj][0] + bov[oj];
                f.y += acc[oj][1] + bov[oj];
                f.z += acc[oj][2] + bov[oj];
                f.w += acc[oj][3] + bov[oj];
                *(float4*)fp = f;
            }
        }
    }
    __syncthreads();
    for (int idx = tid; idx < 4096; idx += 256)
        g_feat[(((size_t)b * 64 + (idx >> 6)) * 64 + y) * 64 + (idx & 63)] = sF[idx];
}

// ---------------- up-sample conv (64->256) + pixel-shuffle + relu ----------------
// tile 32x8 spatial, 64 oc per CTA. 256 thr: ocq=tid&7 (8 oc), pg=tid>>3:
// tx=(pg&3)*8, ty=pg>>2. 8 oc x 8 x per thread.
__global__ void __launch_bounds__(256, 2) k_upconv(int lvl, int IH, int IW,
                                                   const float* __restrict__ up_b) {
    const float* in  = lvl ? g_u1 : g_feat;
    float*       outp = lvl ? g_u2 : g_u1;
    __shared__ float sin_[16][10][36];   // 34 used
    __shared__ float ws [16][9][64];
    int x0 = blockIdx.x * 32, y0 = blockIdx.y * 8;
    int bz = blockIdx.z; int b = bz >> 2; int ocg = bz & 3;
    int tid = threadIdx.x;
    int ocq = tid & 7; int pg = tid >> 3;
    int tx = (pg & 3) * 8; int ty = pg >> 2;
    int ocb = ocg * 64 + ocq * 8;
    float acc[8][8];   // [oc j][xi]
#pragma unroll
    for (int j = 0; j < 8; j++) {
        float bb = up_b[lvl * 256 + ocb + j];
#pragma unroll
        for (int xi = 0; xi < 8; xi++) acc[j][xi] = bb;
    }
    for (int ic0 = 0; ic0 < 64; ic0 += 16) {
        __syncthreads();
        for (int idx = tid; idx < 16 * 10 * 34; idx += 256) {
            int c = idx % 34; int r = (idx / 34) % 10; int icc = idx / 340;
            int gy = y0 - 1 + r, gx = x0 - 1 + c;
            float v = 0.f;
            if (gy >= 0 && gy < IH && gx >= 0 && gx < IW)
                v = in[(((size_t)b * 64 + ic0 + icc) * IH + gy) * IW + gx];
            sin_[icc][r][c] = v;
        }
        for (int idx = tid; idx < 16 * 9 * 64; idx += 256) {
            int oc = idx & 63; int kk = (idx >> 6) % 9; int icc = idx / 576;
            ws[icc][kk][oc] =
                g_wupT[(((lvl * 64 + ic0 + icc) * 9 + kk) * 256) + ocg * 64 + oc];
        }
        __syncthreads();
        for (int icc = 0; icc < 16; icc++) {
#pragma unroll
            for (int ky = 0; ky < 3; ky++) {
                float in10[10];
#pragma unroll
                for (int t = 0; t < 10; t++) in10[t] = sin_[icc][ty + ky][tx + t];
#pragma unroll
                for (int kx = 0; kx < 3; kx++) {
                    float4 wA = *(const float4*)&ws[icc][ky * 3 + kx][ocq * 8];
                    float4 wB = *(const float4*)&ws[icc][ky * 3 + kx][ocq * 8 + 4];
#pragma unroll
                    for (int xi = 0; xi < 8; xi++) {
                        float f = in10[kx + xi];
                        acc[0][xi] += wA.x * f; acc[1][xi] += wA.y * f;
                        acc[2][xi] += wA.z * f; acc[3][xi] += wA.w * f;
                        acc[4][xi] += wB.x * f; acc[5][xi] += wB.y * f;
                        acc[6][xi] += wB.z * f; acc[7][xi] += wB.w * f;
                    }
                }
            }
        }
    }
    int OW = IW * 2;
    int gy = y0 + ty, gxb = x0 + tx;
#pragma unroll
    for (int j = 0; j < 8; j++) {
        int oc4 = ocb + j;
        int c = oc4 >> 2, r1 = (oc4 >> 1) & 1, r2 = oc4 & 1;
        size_t rowbase = (((size_t)b * 64 + c) * (size_t)(IH * 2) + (size_t)(2 * gy + r1)) * (size_t)OW;
#pragma unroll
        for (int xi = 0; xi < 8; xi++)
            outp[rowbase + 2 * (gxb + xi) + r2] = fmaxf(acc[j][xi], 0.f);
    }
}

// ---------------- final conv 64->3 at 256x256 ----------------
__global__ void __launch_bounds__(256) k_cl(const float* __restrict__ w,
                                            const float* __restrict__ bias,
                                            float* __restrict__ out) {
    __shared__ float sw[3 * 64 * 9];
    __shared__ float sin_[4][10][132];
    int xbase = blockIdx.x * 128;
    int y0 = blockIdx.y * 8;
    int b = blockIdx.z;
    int tid = threadIdx.x;
    int xg = tid & 31; int yr = tid >> 5;
    int x0 = xg * 4;
    for (int i = tid; i < 1728; i += 256) sw[i] = w[i];
    float acc[3][4];
#pragma unroll
    for (int oc = 0; oc < 3; oc++) {
        float bb = bias[oc];
#pragma unroll
        for (int xi = 0; xi < 4; xi++) acc[oc][xi] = bb;
    }
    for (int ic0 = 0; ic0 < 64; ic0 += 4) {
        __syncthreads();
        for (int idx = tid; idx < 4 * 10 * 130; idx += 256) {
            int c = idx % 130; int r = (idx / 130) % 10; int icc = idx / 1300;
            int gy = y0 - 1 + r, gx = xbase - 1 + c;
            float v = 0.f;
            if (gy >= 0 && gy < 256 && gx >= 0 && gx < 256)
                v = g_u2[(((size_t)b * 64 + ic0 + icc) * 256 + gy) * 256 + gx];
            sin_[icc][r][c] = v;
        }
        __syncthreads();
        for (int icc = 0; icc < 4; icc++) {
#pragma unroll
            for (int ky = 0; ky < 3; ky++) {
                float in6[6];
#pragma unroll
                for (int t = 0; t < 6; t++) in6[t] = sin_[icc][yr + ky][x0 + t];
#pragma unroll
                for (int kx = 0; kx < 3; kx++) {
#pragma unroll
                    for (int oc = 0; oc < 3; oc++) {
                        float wv = sw[(oc * 64 + ic0 + icc) * 9 + ky * 3 + kx];
#pragma unroll
                        for (int xi = 0; xi < 4; xi++)
                            acc[oc][xi] += wv * in6[kx + xi];
                    }
                }
            }
        }
    }
    int gy = y0 + yr, gx0 = xbase + x0;
#pragma unroll
    for (int oc = 0; oc < 3; oc++) {
        float4 v = make_float4(acc[oc][0], acc[oc][1], acc[oc][2], acc[oc][3]);
        *(float4*)&out[(((size_t)b * 3 + oc) * 256 + gy) * 256 + gx0] = v;
    }
}

// ---------------- launcher ----------------
extern "C" void kernel_launch(void* const* d_in, const int* in_sizes, int n_in,
                              void* d_out, int out_size) {
    const float* x      = (const float*)d_in[0];
    const float* th     = (const float*)d_in[1];
    const float* proj_w = (const float*)d_in[2];
    const float* proj_b = (const float*)d_in[3];
    const float* cf_w   = (const float*)d_in[4];
    const float* cf_b   = (const float*)d_in[5];
    const float* qw     = (const float*)d_in[6];
    const float* qb     = (const float*)d_in[7];
    const float* kw     = (const float*)d_in[8];
    const float* kb     = (const float*)d_in[9];
    const float* vw     = (const float*)d_in[10];
    const float* vb     = (const float*)d_in[11];
    const float* ow     = (const float*)d_in[12];
    const float* ob     = (const float*)d_in[13];
    const float* l1w    = (const float*)d_in[14];
    const float* l1b    = (const float*)d_in[15];
    const float* l2w    = (const float*)d_in[16];
    const float* l2b    = (const float*)d_in[17];
    const float* up_w   = (const float*)d_in[18];
    const float* up_b   = (const float*)d_in[19];
    const float* cl_w   = (const float*)d_in[20];
    const float* cl_b   = (const float*)d_in[21];
    float* out = (float*)d_out;

    k_textproj<<<BATCH * LSEQ, 64>>>(th, proj_w, proj_b, up_w);
    k_convin<<<BATCH * HH, 64>>>(x, cf_w, cf_b);
    k_kvall<<<dim3(NBLK, BATCH, 2), 256>>>(kw, kb, vw, vb, l2w, l2b);
    k_attn_stack<<<BATCH * HH, 256>>>(qw, qb, ow, ob, l1w, l1b);
    k_upconv<<<dim3(2, 8, BATCH * 4), 256>>>(0, 64, 64, up_b);
    k_upconv<<<dim3(4, 16, BATCH * 4), 256>>>(1, 128, 128, up_b);
    k_cl<<<dim3(2, 32, BATCH), 256>>>(cl_w, cl_b, out);

    (void)in_sizes; (void)n_in; (void)out_size;
}

// round 5
// speedup vs baseline: 1.4397x; 1.2442x over previous
#include <cuda_runtime.h>
#include <cuda_bf16.h>
#include <cstdint>

// ---------------- problem constants ----------------
#define BATCH 8
#define CCH   64
#define HH    64
#define WW    64
#define NPOS  4096
#define LSEQ  77
#define DTXT  512
#define NBLK  16
#define NHEAD 8
#define HDIM  8

// ---------------- device scratch ----------------
__device__ float g_tf  [BATCH*LSEQ*CCH];
__device__ float g_kn  [NBLK*BATCH*LSEQ*CCH];
__device__ float g_v   [NBLK*BATCH*LSEQ*CCH];
__device__ float g_feat[BATCH*CCH*HH*WW];
__device__ float g_u1  [BATCH*CCH*128*128];
__device__ float g_u2  [(size_t)BATCH*CCH*256*256];
__device__ float g_wupT[2*9*64*256];          // [lvl][tap][ic][oc4], tf32-rounded

__device__ __forceinline__ float to_tf32(float x) {
    float r; asm("cvt.rna.tf32.f32 %0, %1;" : "=f"(r) : "f"(x)); return r;
}
__device__ __forceinline__ void mma_tf32(float* d, const uint32_t* a, const uint32_t* b) {
    asm volatile(
        "mma.sync.aligned.m16n8k8.row.col.f32.tf32.tf32.f32 "
        "{%0,%1,%2,%3}, {%4,%5,%6,%7}, {%8,%9}, {%0,%1,%2,%3};"
        : "+f"(d[0]), "+f"(d[1]), "+f"(d[2]), "+f"(d[3])
        : "r"(a[0]), "r"(a[1]), "r"(a[2]), "r"(a[3]), "r"(b[0]), "r"(b[1]));
}

// ---------------- text projection (+ fused tf32 up-weight transpose) ----------------
__global__ void k_textproj(const float* __restrict__ th,
                           const float* __restrict__ pw,
                           const float* __restrict__ pb,
                           const float* __restrict__ upw) {
    __shared__ float s[DTXT];
    int bl = blockIdx.x;
    const float* row = th + (size_t)bl * DTXT;
    for (int i = threadIdx.x; i < DTXT; i += 64) s[i] = row[i];
    __syncthreads();
    int c = threadIdx.x;
    const float* w = pw + (size_t)c * DTXT;
    float acc = pb[c];
#pragma unroll 8
    for (int d = 0; d < DTXT; ++d) acc += s[d] * w[d];
    g_tf[bl * CCH + c] = acc;
    // transpose up weights [lvl,oc4,ic,k] -> [lvl,k,ic,oc4], rounded to tf32
    for (int idx = blockIdx.x * 64 + threadIdx.x; idx < 2 * 256 * 64 * 9;
         idx += gridDim.x * 64) {
        int k = idx % 9;
        int t = idx / 9;
        int ic = t % 64; t /= 64;
        int oc4 = t % 256;
        int lvl = t / 256;
        g_wupT[(((lvl * 9 + k) * 64 + ic) * 256) + oc4] = to_tf32(upw[idx]);
    }
}

// ---------------- input conv 3->64, 3x3 ----------------
__global__ void k_convin(const float* __restrict__ x,
                         const float* __restrict__ w,
                         const float* __restrict__ bias) {
    __shared__ float sw[64 * 27];
    __shared__ float sb[64];
    __shared__ float sin_[3][3][66];
    int bid = blockIdx.x; int b = bid >> 6; int y = bid & 63;
    int tid = threadIdx.x;
    for (int i = tid; i < 64 * 27; i += 64) sw[i] = w[i];
    sb[tid] = bias[tid];
    for (int ic = 0; ic < 3; ic++)
        for (int r = 0; r < 3; r++) {
            int yy = y + r - 1;
            float v = 0.f;
            if (yy >= 0 && yy < HH) v = x[(((size_t)b * 3 + ic) * HH + yy) * WW + tid];
            sin_[ic][r][tid + 1] = v;
            if (tid == 0) { sin_[ic][r][0] = 0.f; sin_[ic][r][65] = 0.f; }
        }
    __syncthreads();
    int xx = tid;
    for (int oc = 0; oc < 64; oc++) {
        float acc = sb[oc];
#pragma unroll
        for (int ic = 0; ic < 3; ic++)
#pragma unroll
            for (int r = 0; r < 3; r++)
#pragma unroll
                for (int kx = 0; kx < 3; kx++)
                    acc += sin_[ic][r][xx + kx] * sw[(oc * 3 + ic) * 9 + r * 3 + kx];
        g_feat[(((size_t)b * CCH + oc) * HH + y) * WW + xx] = acc;
    }
}

// ---------------- K/V projection + LN(K), all blocks, L-split ----------------
__global__ void __launch_bounds__(256) k_kvall(
        const float* __restrict__ kw, const float* __restrict__ kb,
        const float* __restrict__ vw, const float* __restrict__ vb,
        const float* __restrict__ l2w, const float* __restrict__ l2b) {
    __shared__ float tfs[LSEQ * 64];
    __shared__ float kws[64 * 68];
    __shared__ float vws[64 * 68];
    __shared__ float ksm[4 * 64];
    int blk = blockIdx.x, b = blockIdx.y, z = blockIdx.z;
    int tid = threadIdx.x;
    for (int i = tid; i < LSEQ * 64; i += 256) tfs[i] = g_tf[b * LSEQ * 64 + i];
    for (int idx = tid; idx < 4096; idx += 256) {
        int o = idx >> 6, c = idx & 63;
        kws[c * 68 + o] = kw[blk * 4096 + idx];
        vws[c * 68 + o] = vw[blk * 4096 + idx];
    }
    __syncthreads();
    int o = tid & 63, rr = tid >> 6;
    float kbv = kb[blk * 64 + o], vbv = vb[blk * 64 + o];
    float lwv = l2w[blk * 64 + o], lbv = l2b[blk * 64 + o];
    size_t base = ((size_t)(blk * BATCH + b)) * LSEQ * 64;
    int rbeg = z * 40, rend = rbeg + 40;
    for (int r0 = rbeg; r0 < rend; r0 += 4) {
        int r = r0 + rr;
        bool act = r < LSEQ;
        float ka = kbv, va = vbv;
        if (act) {
#pragma unroll 8
            for (int c = 0; c < 64; c++) {
                float t = tfs[r * 64 + c];
                ka += t * kws[c * 68 + o];
                va += t * vws[c * 68 + o];
            }
            ksm[rr * 64 + o] = ka;
        }
        __syncthreads();
        if (act) {
            float m = 0.f;
#pragma unroll 8
            for (int i = 0; i < 64; i++) m += ksm[rr * 64 + i];
            m *= (1.f / 64.f);
            float vv = 0.f;
#pragma unroll 8
            for (int i = 0; i < 64; i++) { float d = ksm[rr * 64 + i] - m; vv += d * d; }
            vv *= (1.f / 64.f);
            float rs = rsqrtf(vv + 1e-5f);
            g_kn[base + r * 64 + o] = (ka - m) * rs * lwv + lbv;
            g_v [base + r * 64 + o] = va;
        }
        __syncthreads();
    }
}

// ---------------- FUSED attention stack (unchanged from R4) ----------------
__global__ void __launch_bounds__(256, 3) k_attn_stack(
        const float* __restrict__ qw, const float* __restrict__ qb,
        const float* __restrict__ ow, const float* __restrict__ ob,
        const float* __restrict__ l1w, const float* __restrict__ l1b) {
    __shared__ __align__(16) float rA[LSEQ * 64];
    __shared__ __align__(16) float rB[LSEQ * 64];
    __shared__ __align__(16) float sF[64 * 64];
    __shared__ __align__(16) float sQ[64 * 68];

    int b = blockIdx.x >> 6, y = blockIdx.x & 63;
    int tid = threadIdx.x;

    for (int idx = tid; idx < 4096; idx += 256)
        sF[idx] = g_feat[(((size_t)b * 64 + (idx >> 6)) * 64 + y) * 64 + (idx & 63)];

    float pey = (float)y * (0.05f / 63.f);
    const float scale = 0.35355339059327373f;

#pragma unroll 1
    for (int blk = 0; blk < NBLK; blk++) {
        size_t kvbase = ((size_t)(blk * BATCH + b)) * LSEQ * 64;
        __syncthreads();
        for (int idx = tid; idx < 4096; idx += 256) {
            int o = idx >> 6, i = idx & 63;
            rA[i * 68 + o] = qw[blk * 4096 + idx];
        }
        for (int i = tid; i < LSEQ * 64; i += 256) rB[i] = g_v[kvbase + i];
        __syncthreads();

        {
            int og = tid & 15, xg = tid >> 4;
            int o0 = og * 4, x0 = xg * 4;
            float4 bq = *(const float4*)&qb[blk * 64 + o0];
            float acc[4][4];
#pragma unroll
            for (int xi = 0; xi < 4; xi++) {
                acc[xi][0] = bq.x; acc[xi][1] = bq.y; acc[xi][2] = bq.z; acc[xi][3] = bq.w;
            }
#pragma unroll 8
            for (int i = 0; i < 64; i++) {
                float4 fx = *(const float4*)&sF[i * 64 + x0];
                float4 wv = *(const float4*)&rA[i * 68 + o0];
                acc[0][0] += fx.x * wv.x; acc[0][1] += fx.x * wv.y; acc[0][2] += fx.x * wv.z; acc[0][3] += fx.x * wv.w;
                acc[1][0] += fx.y * wv.x; acc[1][1] += fx.y * wv.y; acc[1][2] += fx.y * wv.z; acc[1][3] += fx.y * wv.w;
                acc[2][0] += fx.z * wv.x; acc[2][1] += fx.z * wv.y; acc[2][2] += fx.z * wv.z; acc[2][3] += fx.z * wv.w;
                acc[3][0] += fx.w * wv.x; acc[3][1] += fx.w * wv.y; acc[3][2] += fx.w * wv.z; acc[3][3] += fx.w * wv.w;
            }
            float4 lw = *(const float4*)&l1w[blk * 64 + o0];
            float4 lb = *(const float4*)&l1b[blk * 64 + o0];
#pragma unroll
            for (int xi = 0; xi < 4; xi++) {
                float pex = (float)(x0 + xi) * (0.05f / 63.f);
#pragma unroll
                for (int oj = 0; oj < 4; oj++)
                    acc[xi][oj] += ((o0 + oj) < 32) ? pex : pey;
                float s = acc[xi][0] + acc[xi][1] + acc[xi][2] + acc[xi][3];
#pragma unroll
                for (int off = 1; off < 16; off <<= 1) s += __shfl_xor_sync(0xffffffffu, s, off);
                float mean = s * (1.f / 64.f);
                float d0 = acc[xi][0] - mean, d1 = acc[xi][1] - mean,
                      d2 = acc[xi][2] - mean, d3 = acc[xi][3] - mean;
                float sq = d0 * d0 + d1 * d1 + d2 * d2 + d3 * d3;
#pragma unroll
                for (int off = 1; off < 16; off <<= 1) sq += __shfl_xor_sync(0xffffffffu, sq, off);
                float rs = rsqrtf(sq * (1.f / 64.f) + 1e-5f);
                float4 outv;
                outv.x = d0 * rs * lw.x + lb.x;
                outv.y = d1 * rs * lw.y + lb.y;
                outv.z = d2 * rs * lw.z + lb.z;
                outv.w = d3 * rs * lw.w + lb.w;
                *(float4*)&sQ[(x0 + xi) * 68 + o0] = outv;
            }
        }
        __syncthreads();
        for (int i = tid; i < LSEQ * 64; i += 256) rA[i] = g_kn[kvbase + i];
        __syncthreads();

        {
            int hp = tid & 3, pl = tid >> 2;
            int co = hp * 16;
            const float4* qp = (const float4*)&sQ[pl * 68 + co];
            float4 qa0 = qp[0], qa1 = qp[1], qb0 = qp[2], qb1 = qp[3];
            __syncthreads();
            float denA = 0.f, denB = 0.f;
            float4 a0 = make_float4(0, 0, 0, 0), a1 = a0, b0 = a0, b1 = a0;
            for (int l = 0; l < LSEQ; l++) {
                const float4* kp = (const float4*)&rA[l * 64 + co];
                float4 k0 = kp[0], k1 = kp[1], k2 = kp[2], k3 = kp[3];
                float lgA = qa0.x * k0.x + qa0.y * k0.y + qa0.z * k0.z + qa0.w * k0.w
                          + qa1.x * k1.x + qa1.y * k1.y + qa1.z * k1.z + qa1.w * k1.w;
                float lgB = qb0.x * k2.x + qb0.y * k2.y + qb0.z * k2.z + qb0.w * k2.w
                          + qb1.x * k3.x + qb1.y * k3.y + qb1.z * k3.z + qb1.w * k3.w;
                float eA = __expf(lgA * scale);
                float eB = __expf(lgB * scale);
                denA += eA; denB += eB;
                const float4* vp = (const float4*)&rB[l * 64 + co];
                float4 v0 = vp[0], v1 = vp[1], v2 = vp[2], v3 = vp[3];
                a0.x += eA * v0.x; a0.y += eA * v0.y; a0.z += eA * v0.z; a0.w += eA * v0.w;
                a1.x += eA * v1.x; a1.y += eA * v1.y; a1.z += eA * v1.z; a1.w += eA * v1.w;
                b0.x += eB * v2.x; b0.y += eB * v2.y; b0.z += eB * v2.z; b0.w += eB * v2.w;
                b1.x += eB * v3.x; b1.y += eB * v3.y; b1.z += eB * v3.z; b1.w += eB * v3.w;
            }
            float iA = 1.f / denA, iB = 1.f / denB;
            sQ[(co + 0) * 68 + pl] = a0.x * iA;  sQ[(co + 1) * 68 + pl] = a0.y * iA;
            sQ[(co + 2) * 68 + pl] = a0.z * iA;  sQ[(co + 3) * 68 + pl] = a0.w * iA;
            sQ[(co + 4) * 68 + pl] = a1.x * iA;  sQ[(co + 5) * 68 + pl] = a1.y * iA;
            sQ[(co + 6) * 68 + pl] = a1.z * iA;  sQ[(co + 7) * 68 + pl] = a1.w * iA;
            sQ[(co + 8) * 68 + pl] = b0.x * iB;  sQ[(co + 9) * 68 + pl] = b0.y * iB;
            sQ[(co + 10) * 68 + pl] = b0.z * iB; sQ[(co + 11) * 68 + pl] = b0.w * iB;
            sQ[(co + 12) * 68 + pl] = b1.x * iB; sQ[(co + 13) * 68 + pl] = b1.y * iB;
            sQ[(co + 14) * 68 + pl] = b1.z * iB; sQ[(co + 15) * 68 + pl] = b1.w * iB;
        }
        __syncthreads();
        for (int idx = tid; idx < 4096; idx += 256) {
            int o = idx >> 6, i = idx & 63;
            rB[i * 68 + o] = ow[blk * 4096 + idx];
        }
        __syncthreads();

        {
            int xg = tid & 15, og = tid >> 4;
            int x0 = xg * 4, o0 = og * 4;
            float acc[4][4];
#pragma unroll
            for (int oj = 0; oj < 4; oj++)
#pragma unroll
                for (int xi = 0; xi < 4; xi++) acc[oj][xi] = 0.f;
#pragma unroll 8
            for (int i = 0; i < 64; i++) {
                float4 fx = *(const float4*)&sQ[i * 68 + x0];
                float4 wv = *(const float4*)&rB[i * 68 + o0];
                acc[0][0] += wv.x * fx.x; acc[0][1] += wv.x * fx.y; acc[0][2] += wv.x * fx.z; acc[0][3] += wv.x * fx.w;
                acc[1][0] += wv.y * fx.x; acc[1][1] += wv.y * fx.y; acc[1][2] += wv.y * fx.z; acc[1][3] += wv.y * fx.w;
                acc[2][0] += wv.z * fx.x; acc[2][1] += wv.z * fx.y; acc[2][2] += wv.z * fx.z; acc[2][3] += wv.z * fx.w;
                acc[3][0] += wv.w * fx.x; acc[3][1] += wv.w * fx.y; acc[3][2] += wv.w * fx.z; acc[3][3] += wv.w * fx.w;
            }
            float4 bo = *(const float4*)&ob[blk * 64 + o0];
            float bov[4] = { bo.x, bo.y, bo.z, bo.w };
            __syncthreads();
#pragma unroll
            for (int oj = 0; oj < 4; oj++) {
                float* fp = &sF[(o0 + oj) * 64 + x0];
                float4 f = *(float4*)fp;
                f.x += acc[oj][0] + bov[oj];
                f.y += acc[oj][1] + bov[oj];
                f.z += acc[oj][2] + bov[oj];
                f.w += acc[oj][3] + bov[oj];
                *(float4*)fp = f;
            }
        }
    }
    __syncthreads();
    for (int idx = tid; idx < 4096; idx += 256)
        g_feat[(((size_t)b * 64 + (idx >> 6)) * 64 + y) * 64 + (idx & 63)] = sF[idx];
}

// ---------------- TF32 tensor-core up-conv + pixel-shuffle + relu ----------------
// CTA: 16x8 spatial (M=128) x 64 oc (N=64). K=576 = 9 taps x 64 ic.
// 8 warps: wm = w&3 (M 4x32), wn = w>>2 (N 2x32). Warp tile 32x32.
__global__ void __launch_bounds__(256, 3) k_upconv_tc(int lvl, int IH, int IW,
                                                      const float* __restrict__ up_b) {
    const float* in   = lvl ? g_u1 : g_feat;
    float*       outp = lvl ? g_u2 : g_u1;
    __shared__ float sA[180 * 66];   // [spatial r*18+c][ic], stride 66
    __shared__ float sB[64 * 65];    // [ic][oc], stride 65
    int x0 = blockIdx.x * 16, y0 = blockIdx.y * 8;
    int bz = blockIdx.z; int b = bz >> 2, ocg = bz & 3;
    int tid = threadIdx.x;
    int w = tid >> 5, lane = tid & 31;
    int g = lane >> 2, tig = lane & 3;
    int wm = w & 3, wn = w >> 2;

    // stage input tile with halo, rounded to tf32
    for (int idx = tid; idx < 180 * 64; idx += 256) {
        int ic = idx / 180; int sp = idx % 180;
        int r = sp / 18, c = sp % 18;
        int gy = y0 - 1 + r, gx = x0 - 1 + c;
        float v = 0.f;
        if (gy >= 0 && gy < IH && gx >= 0 && gx < IW)
            v = in[(((size_t)b * 64 + ic) * IH + gy) * IW + gx];
        sA[sp * 66 + ic] = to_tf32(v);
    }

    // accumulators init with bias: oc = ocg*64 + wn*32 + nt*8 + tig*2 (+1)
    float d[2][4][4];
#pragma unroll
    for (int nt = 0; nt < 4; nt++) {
        int oc = ocg * 64 + wn * 32 + nt * 8 + tig * 2;
        float b0v = up_b[lvl * 256 + oc];
        float b1v = up_b[lvl * 256 + oc + 1];
#pragma unroll
        for (int mt = 0; mt < 2; mt++) {
            d[mt][nt][0] = b0v; d[mt][nt][1] = b1v;
            d[mt][nt][2] = b0v; d[mt][nt][3] = b1v;
        }
    }

#pragma unroll 1
    for (int t = 0; t < 9; t++) {
        int ky = t / 3, kx = t % 3;
        __syncthreads();   // sA visible (t=0) / prior mma done with sB
        for (int idx = tid; idx < 4096; idx += 256) {
            int ic = idx >> 6, oc = idx & 63;
            sB[ic * 65 + oc] = g_wupT[(((lvl * 9 + t) * 64 + ic) * 256) + ocg * 64 + oc];
        }
        __syncthreads();
        // precompute A spatial offsets for this tap
        int sp_base[2][2];   // [mt][lo/hi]
#pragma unroll
        for (int mt = 0; mt < 2; mt++) {
            int m_lo = wm * 32 + mt * 16 + g;
            int m_hi = m_lo + 8;
            sp_base[mt][0] = ((m_lo >> 4) + ky) * 18 + (m_lo & 15) + kx;
            sp_base[mt][1] = ((m_hi >> 4) + ky) * 18 + (m_hi & 15) + kx;
        }
#pragma unroll
        for (int ks = 0; ks < 8; ks++) {
            int ic0 = ks * 8;
            uint32_t A[2][4];
#pragma unroll
            for (int mt = 0; mt < 2; mt++) {
                A[mt][0] = __float_as_uint(sA[sp_base[mt][0] * 66 + ic0 + tig]);
                A[mt][1] = __float_as_uint(sA[sp_base[mt][1] * 66 + ic0 + tig]);
                A[mt][2] = __float_as_uint(sA[sp_base[mt][0] * 66 + ic0 + tig + 4]);
                A[mt][3] = __float_as_uint(sA[sp_base[mt][1] * 66 + ic0 + tig + 4]);
            }
            uint32_t Bf[4][2];
#pragma unroll
            for (int nt = 0; nt < 4; nt++) {
                int nc = wn * 32 + nt * 8 + g;
                Bf[nt][0] = __float_as_uint(sB[(ic0 + tig) * 65 + nc]);
                Bf[nt][1] = __float_as_uint(sB[(ic0 + tig + 4) * 65 + nc]);
            }
#pragma unroll
            for (int mt = 0; mt < 2; mt++)
#pragma unroll
                for (int nt = 0; nt < 4; nt++)
                    mma_tf32(d[mt][nt], A[mt], Bf[nt]);
        }
    }

    // store: pixel shuffle + relu
    int OW = IW * 2;
#pragma unroll
    for (int mt = 0; mt < 2; mt++) {
#pragma unroll
        for (int half = 0; half < 2; half++) {
            int m = wm * 32 + mt * 16 + g + half * 8;
            int gy = y0 + (m >> 4), gx = x0 + (m & 15);
#pragma unroll
            for (int nt = 0; nt < 4; nt++) {
                int oc4a = ocg * 64 + wn * 32 + nt * 8 + tig * 2;
                float v0 = d[mt][nt][half * 2 + 0];
                float v1 = d[mt][nt][half * 2 + 1];
                int ca = oc4a >> 2, r1a = (oc4a >> 1) & 1, r2a = oc4a & 1;
                int oc4b = oc4a + 1;
                int cb = oc4b >> 2, r1b = (oc4b >> 1) & 1, r2b = oc4b & 1;
                outp[(((size_t)b * 64 + ca) * (size_t)(IH * 2) + (size_t)(2 * gy + r1a)) * (size_t)OW
                     + 2 * gx + r2a] = fmaxf(v0, 0.f);
                outp[(((size_t)b * 64 + cb) * (size_t)(IH * 2) + (size_t)(2 * gy + r1b)) * (size_t)OW
                     + 2 * gx + r2b] = fmaxf(v1, 0.f);
            }
        }
    }
}

// ---------------- final conv 64->3 at 256x256 ----------------
__global__ void __launch_bounds__(256) k_cl(const float* __restrict__ w,
                                            const float* __restrict__ bias,
                                            float* __restrict__ out) {
    __shared__ float sw[3 * 64 * 9];
    __shared__ float sin_[4][10][132];
    int xbase = blockIdx.x * 128;
    int y0 = blockIdx.y * 8;
    int b = blockIdx.z;
    int tid = threadIdx.x;
    int xg = tid & 31; int yr = tid >> 5;
    int x0 = xg * 4;
    for (int i = tid; i < 1728; i += 256) sw[i] = w[i];
    float acc[3][4];
#pragma unroll
    for (int oc = 0; oc < 3; oc++) {
        float bb = bias[oc];
#pragma unroll
        for (int xi = 0; xi < 4; xi++) acc[oc][xi] = bb;
    }
    for (int ic0 = 0; ic0 < 64; ic0 += 4) {
        __syncthreads();
        for (int idx = tid; idx < 4 * 10 * 130; idx += 256) {
            int c = idx % 130; int r = (idx / 130) % 10; int icc = idx / 1300;
            int gy = y0 - 1 + r, gx = xbase - 1 + c;
            float v = 0.f;
            if (gy >= 0 && gy < 256 && gx >= 0 && gx < 256)
                v = g_u2[(((size_t)b * 64 + ic0 + icc) * 256 + gy) * 256 + gx];
            sin_[icc][r][c] = v;
        }
        __syncthreads();
        for (int icc = 0; icc < 4; icc++) {
#pragma unroll
            for (int ky = 0; ky < 3; ky++) {
                float in6[6];
#pragma unroll
                for (int t = 0; t < 6; t++) in6[t] = sin_[icc][yr + ky][x0 + t];
#pragma unroll
                for (int kx = 0; kx < 3; kx++) {
#pragma unroll
                    for (int oc = 0; oc < 3; oc++) {
                        float wv = sw[(oc * 64 + ic0 + icc) * 9 + ky * 3 + kx];
#pragma unroll
                        for (int xi = 0; xi < 4; xi++)
                            acc[oc][xi] += wv * in6[kx + xi];
                    }
                }
            }
        }
    }
    int gy = y0 + yr, gx0 = xbase + x0;
#pragma unroll
    for (int oc = 0; oc < 3; oc++) {
        float4 v = make_float4(acc[oc][0], acc[oc][1], acc[oc][2], acc[oc][3]);
        *(float4*)&out[(((size_t)b * 3 + oc) * 256 + gy) * 256 + gx0] = v;
    }
}

// ---------------- launcher ----------------
extern "C" void kernel_launch(void* const* d_in, const int* in_sizes, int n_in,
                              void* d_out, int out_size) {
    const float* x      = (const float*)d_in[0];
    const float* th     = (const float*)d_in[1];
    const float* proj_w = (const float*)d_in[2];
    const float* proj_b = (const float*)d_in[3];
    const float* cf_w   = (const float*)d_in[4];
    const float* cf_b   = (const float*)d_in[5];
    const float* qw     = (const float*)d_in[6];
    const float* qb     = (const float*)d_in[7];
    const float* kw     = (const float*)d_in[8];
    const float* kb     = (const float*)d_in[9];
    const float* vw     = (const float*)d_in[10];
    const float* vb     = (const float*)d_in[11];
    const float* ow     = (const float*)d_in[12];
    const float* ob     = (const float*)d_in[13];
    const float* l1w    = (const float*)d_in[14];
    const float* l1b    = (const float*)d_in[15];
    const float* l2w    = (const float*)d_in[16];
    const float* l2b    = (const float*)d_in[17];
    const float* up_w   = (const float*)d_in[18];
    const float* up_b   = (const float*)d_in[19];
    const float* cl_w   = (const float*)d_in[20];
    const float* cl_b   = (const float*)d_in[21];
    float* out = (float*)d_out;

    k_textproj<<<BATCH * LSEQ, 64>>>(th, proj_w, proj_b, up_w);
    k_convin<<<BATCH * HH, 64>>>(x, cf_w, cf_b);
    k_kvall<<<dim3(NBLK, BATCH, 2), 256>>>(kw, kb, vw, vb, l2w, l2b);
    k_attn_stack<<<BATCH * HH, 256>>>(qw, qb, ow, ob, l1w, l1b);
    k_upconv_tc<<<dim3(4, 8, BATCH * 4), 256>>>(0, 64, 64, up_b);
    k_upconv_tc<<<dim3(8, 16, BATCH * 4), 256>>>(1, 128, 128, up_b);
    k_cl<<<dim3(2, 32, BATCH), 256>>>(cl_w, cl_b, out);

    (void)in_sizes; (void)n_in; (void)out_size;
}